// round 8
// baseline (speedup 1.0000x reference)
#include <cuda_runtime.h>
#include <math_constants.h>
#include <cstdint>

#define C        32000
#define CHALF    16000
#define CHALF4   (CHALF / 4)        // 4000 float4 per half-row
#define GRID_PTS 100
#define NMIDS    (GRID_PTS - 1)
#define THREADS  1024
#define NWARP    (THREADS / 32)

// smem floats: xbuf[CHALF] | thr[NMIDS] | ybuf[GRID_PTS] | red[NWARP] | maxbox | sumbox
#define OFF_THR   CHALF
#define OFF_Y     (OFF_THR + NMIDS)
#define OFF_RED   (OFF_Y + GRID_PTS)
#define OFF_MAXB  (OFF_RED + NWARP)
#define OFF_SUMB  (OFF_MAXB + 1)
#define SMEM_FLOATS (OFF_SUMB + 1)
#define SMEM_BYTES  (SMEM_FLOATS * sizeof(float))

__device__ __forceinline__ uint32_t smem_u32(const void* p) {
    uint32_t a;
    asm("{ .reg .u64 t; cvta.to.shared.u64 t, %1; cvt.u32.u64 %0, t; }"
        : "=r"(a) : "l"(p));
    return a;
}

__device__ __forceinline__ void cluster_sync_() {
    asm volatile("barrier.cluster.arrive.aligned;" ::: "memory");
    asm volatile("barrier.cluster.wait.aligned;" ::: "memory");
}

__device__ __forceinline__ float peer_smem_f32(uint32_t local_addr, uint32_t peer_rank) {
    uint32_t raddr;
    asm("mapa.shared::cluster.u32 %0, %1, %2;" : "=r"(raddr) : "r"(local_addr), "r"(peer_rank));
    float v;
    asm volatile("ld.shared::cluster.f32 %0, [%1];" : "=f"(v) : "r"(raddr));
    return v;
}

__global__ __launch_bounds__(THREADS, 2) __cluster_dims__(2, 1, 1)
void calib_kernel(const float* __restrict__ logits,
                  const float* __restrict__ log_temp,
                  const float* __restrict__ iso_x,
                  const float* __restrict__ iso_y,
                  float* __restrict__ out)
{
    extern __shared__ float smem[];
    float* xbuf = smem;               // CHALF
    float* thr  = smem + OFF_THR;     // NMIDS  log-domain thresholds
    float* ybuf = smem + OFF_Y;       // GRID_PTS
    float* red  = smem + OFF_RED;     // NWARP

    const int tid  = threadIdx.x;
    const int lane = tid & 31;
    const int wid  = tid >> 5;

    const int row  = blockIdx.x >> 1;
    const uint32_t half = blockIdx.x & 1u;   // == cluster rank
    const uint32_t peer = half ^ 1u;

    const uint32_t maxbox_a = smem_u32(smem + OFF_MAXB);
    const uint32_t sumbox_a = smem_u32(smem + OFF_SUMB);

    // temperature = clamp(exp(log_T), 0.1, 10); fold log2(e)/T into the scale
    const float T  = fminf(fmaxf(expf(log_temp[0]), 0.1f), 10.0f);
    const float s2 = 1.4426950408889634f / T;   // base-2 scale

    if (tid < GRID_PTS) ybuf[tid] = iso_y[tid];

    const long long base = (long long)row * C + (long long)half * CHALF;
    const float4* lg4  = reinterpret_cast<const float4*>(logits + base);
    float4*       out4 = reinterpret_cast<float4*>(out + base);
    float4*       x4   = reinterpret_cast<float4*>(xbuf);

    // ---- Phase 1: single HBM read; scale; stage to smem; local max ----
    float m = -CUDART_INF_F;
    #pragma unroll 4
    for (int i = tid; i < CHALF4; i += THREADS) {
        float4 v = lg4[i];
        v.x *= s2; v.y *= s2; v.z *= s2; v.w *= s2;
        x4[i] = v;
        m = fmaxf(m, fmaxf(fmaxf(v.x, v.y), fmaxf(v.z, v.w)));
    }
    #pragma unroll
    for (int o = 16; o; o >>= 1) m = fmaxf(m, __shfl_xor_sync(0xffffffffu, m, o));
    if (lane == 0) red[wid] = m;
    __syncthreads();
    if (wid == 0) {
        float mm = red[lane];
        #pragma unroll
        for (int o = 16; o; o >>= 1) mm = fmaxf(mm, __shfl_xor_sync(0xffffffffu, mm, o));
        if (lane == 0) smem[OFF_MAXB] = mm;
    }
    __syncthreads();
    // exchange max with peer CTA
    cluster_sync_();
    const float M = fmaxf(smem[OFF_MAXB], peer_smem_f32(maxbox_a, peer));
    __syncthreads();   // red[] reuse guard

    // ---- Phase 2: local sum of 2^(x - M); no writeback ----
    float s = 0.0f;
    #pragma unroll 4
    for (int i = tid; i < CHALF4; i += THREADS) {
        float4 v = x4[i];
        s += exp2f(v.x - M) + exp2f(v.y - M) + exp2f(v.z - M) + exp2f(v.w - M);
    }
    #pragma unroll
    for (int o = 16; o; o >>= 1) s += __shfl_xor_sync(0xffffffffu, s, o);
    if (lane == 0) red[wid] = s;
    __syncthreads();
    if (wid == 0) {
        float ss = red[lane];
        #pragma unroll
        for (int o = 16; o; o >>= 1) ss += __shfl_xor_sync(0xffffffffu, ss, o);
        if (lane == 0) smem[OFF_SUMB] = ss;
    }
    __syncthreads();
    // exchange sum with peer CTA
    cluster_sync_();
    const float S = smem[OFF_SUMB] + peer_smem_f32(sumbox_a, peer);

    // Log-domain thresholds:
    //   mids[i]*S < 2^(x-M)  <=>  log2(mids[i]*S) + M < x
    if (tid < NMIDS)
        thr[tid] = log2f(0.5f * (iso_x[tid] + iso_x[tid + 1]) * S) + M;
    __syncthreads();

    const float L0 = thr[0];
    const float y0 = ybuf[0];

    // ---- Phase 3: compare staged scaled logits vs thresholds; single HBM write ----
    #pragma unroll 4
    for (int i = tid; i < CHALF4; i += THREADS) {
        float4 v = x4[i];
        float4 r;
        float* vp = &v.x;
        float* rp = &r.x;
        #pragma unroll
        for (int k = 0; k < 4; k++) {
            float xv = vp[k];
            if (xv <= L0) {
                rp[k] = y0;               // warp-uniform fast path (~all of a softmax row)
            } else {
                int lo = 1, hi = NMIDS;   // thr[0] < xv already known
                while (lo < hi) {
                    int mid = (lo + hi) >> 1;
                    if (thr[mid] < xv) lo = mid + 1; else hi = mid;
                }
                rp[k] = ybuf[lo];
            }
        }
        out4[i] = r;
    }
}

extern "C" void kernel_launch(void* const* d_in, const int* in_sizes, int n_in,
                              void* d_out, int out_size) {
    const float* logits   = (const float*)d_in[0];
    const float* log_temp = (const float*)d_in[1];
    const float* iso_x    = (const float*)d_in[2];
    const float* iso_y    = (const float*)d_in[3];
    float* out = (float*)d_out;

    const int rows = out_size / C;

    cudaFuncSetAttribute(calib_kernel,
                         cudaFuncAttributeMaxDynamicSharedMemorySize,
                         (int)SMEM_BYTES);
    calib_kernel<<<rows * 2, THREADS, SMEM_BYTES>>>(logits, log_temp, iso_x, iso_y, out);
}

// round 10
// speedup vs baseline: 1.4351x; 1.4351x over previous
#include <cuda_runtime.h>
#include <math_constants.h>
#include <cstdint>

#define C        32000
#define C4       (C / 4)            // 8000 float4 per row
#define GRID_PTS 100
#define NMIDS    (GRID_PTS - 1)
#define THREADS  1024
#define NWARP    (THREADS / 32)     // 32

__global__ __launch_bounds__(THREADS, 2)
void calib_kernel(const float* __restrict__ logits,
                  const float* __restrict__ log_temp,
                  const float* __restrict__ iso_x,
                  const float* __restrict__ iso_y,
                  float* __restrict__ out)
{
    __shared__ float thr[NMIDS];        // log-domain thresholds
    __shared__ float ybuf[GRID_PTS];
    __shared__ float redm[NWARP];
    __shared__ float reds[NWARP];
    __shared__ float fin[2];            // M, S

    const int tid  = threadIdx.x;
    const int lane = tid & 31;
    const int wid  = tid >> 5;
    const long long row = blockIdx.x;

    // temperature = clamp(exp(log_T), 0.1, 10); fold log2(e)/T into the scale
    const float T  = fminf(fmaxf(expf(log_temp[0]), 0.1f), 10.0f);
    const float s2 = 1.4426950408889634f / T;   // base-2 scale

    if (tid < GRID_PTS) ybuf[tid] = iso_y[tid];

    const float4* lg4  = reinterpret_cast<const float4*>(logits + row * (long long)C);
    float4*       out4 = reinterpret_cast<float4*>(out + row * (long long)C);

    // ---- Phase 1: single streaming HBM read with fused online softmax (m, s) ----
    float m = -CUDART_INF_F;
    float s = 0.0f;
    #pragma unroll 4
    for (int i = tid; i < C4; i += THREADS) {
        float4 v = lg4[i];
        v.x *= s2; v.y *= s2; v.z *= s2; v.w *= s2;
        float mx = fmaxf(fmaxf(v.x, v.y), fmaxf(v.z, v.w));
        if (mx > m) {                      // rare: ~log(n) times per thread
            s *= exp2f(m - mx);            // exp2f(-inf)=0 handles first iter
            m = mx;
        }
        // 4 independent MUFUs, hidden under the LDG stream
        s += (exp2f(v.x - m) + exp2f(v.y - m)) + (exp2f(v.z - m) + exp2f(v.w - m));
    }

    // warp-level (m, s) combine
    #pragma unroll
    for (int o = 16; o; o >>= 1) {
        float mo = __shfl_xor_sync(0xffffffffu, m, o);
        float so = __shfl_xor_sync(0xffffffffu, s, o);
        float nm = fmaxf(m, mo);
        s = s * exp2f(m - nm) + so * exp2f(mo - nm);
        m = nm;
    }
    if (lane == 0) { redm[wid] = m; reds[wid] = s; }
    __syncthreads();
    if (wid == 0) {
        float mm = redm[lane];              // NWARP == 32: every lane valid
        float ss = reds[lane];
        #pragma unroll
        for (int o = 16; o; o >>= 1) {
            float mo = __shfl_xor_sync(0xffffffffu, mm, o);
            float so = __shfl_xor_sync(0xffffffffu, ss, o);
            float nm = fmaxf(mm, mo);
            ss = ss * exp2f(mm - nm) + so * exp2f(mo - nm);
            mm = nm;
        }
        if (lane == 0) { fin[0] = mm; fin[1] = ss; }
    }
    __syncthreads();
    const float M = fin[0];
    const float S = fin[1];

    // Log-domain thresholds:  mids[i]*S < 2^(x-M)  <=>  log2(mids[i]*S) + M < x
    if (tid < NMIDS)
        thr[tid] = log2f(0.5f * (iso_x[tid] + iso_x[tid + 1]) * S) + M;
    __syncthreads();

    const float L0 = thr[0];
    const float y0 = ybuf[0];

    // ---- Phase 2: re-read logits (L2-resident), bin, single HBM write ----
    #pragma unroll 4
    for (int i = tid; i < C4; i += THREADS) {
        float4 v = lg4[i];
        v.x *= s2; v.y *= s2; v.z *= s2; v.w *= s2;   // bit-identical to phase 1
        float4 r;
        float* vp = &v.x;
        float* rp = &r.x;
        #pragma unroll
        for (int k = 0; k < 4; k++) {
            float xv = vp[k];
            if (xv <= L0) {
                rp[k] = y0;               // warp-uniform fast path (~all of a softmax row)
            } else {
                int lo = 1, hi = NMIDS;   // thr[0] < xv already established
                while (lo < hi) {
                    int mid = (lo + hi) >> 1;
                    if (thr[mid] < xv) lo = mid + 1; else hi = mid;
                }
                rp[k] = ybuf[lo];
            }
        }
        out4[i] = r;
    }
}

extern "C" void kernel_launch(void* const* d_in, const int* in_sizes, int n_in,
                              void* d_out, int out_size) {
    const float* logits   = (const float*)d_in[0];
    const float* log_temp = (const float*)d_in[1];
    const float* iso_x    = (const float*)d_in[2];
    const float* iso_y    = (const float*)d_in[3];
    float* out = (float*)d_out;

    const int rows = out_size / C;
    calib_kernel<<<rows, THREADS>>>(logits, log_temp, iso_x, iso_y, out);
}